// round 5
// baseline (speedup 1.0000x reference)
#include <cuda_runtime.h>
#include <cuda_bf16.h>

// x:       (L=2048, B=16) int32   -> x[l*16 + b]
// embed_w: (V=50257, D=1024) fp32 -> w[t*1024 + d]
// out:     (B=16, D=1024, L=2048) fp32 -> out[b*D*L + d*L + l]
// rows with token >= 20 are zero; output scaled by sqrt(8).

#define L_DIM   2048
#define B_DIM   16
#define D_DIM   1024
#define MAXTOK  20
#define SCALE   2.8284271247461903f  // sqrt(8)

#define ZBLOCKS 4096
#define ZTPB    256
#define ZITER   8            // 4096*256*8 = 8388608 float4
#define STRIDE  (1u << 20)   // ZBLOCKS*ZTPB

// 512 l4-groups (l4 = l/4). Bit g of mask = any token < MAXTOK among
// l in [4g, 4g+4) at ANY b. 512 bits = 16 words.
__device__ unsigned g_mask[16];

// ---------------------------------------------------------------------------
// Kernel 1: build the 512-bit predicate mask. 16 blocks x 1 warp.
// Warp w covers groups [32w, 32w+32) = ints [2048w, 2048w+2048) = 512 int4,
// read fully coalesced; ballot-reduce 16 ints -> 1 group bit.
// ---------------------------------------------------------------------------
__global__ void __launch_bounds__(32) mask_kernel(const int* __restrict__ x)
{
    const int wi   = blockIdx.x;          // word index 0..15
    const int lane = threadIdx.x;
    const int4* src = (const int4*)x + wi * 512;

    unsigned word = 0;
    #pragma unroll
    for (int j = 0; j < 16; j++) {
        int4 v = __ldg(src + j * 32 + lane);   // coalesced 512B per load
        int hit = (v.x < MAXTOK) | (v.y < MAXTOK) |
                  (v.z < MAXTOK) | (v.w < MAXTOK);
        unsigned bal = __ballot_sync(0xFFFFFFFFu, hit);
        // int4 (j*32+lane) belongs to relative group 2j + (lane>=16)
        word |= ((bal & 0xFFFFu) ? 1u : 0u) << (2 * j);
        word |= ((bal >> 16)     ? 1u : 0u) << (2 * j + 1);
    }
    if (lane == 0) g_mask[wi] = word;
}

// ---------------------------------------------------------------------------
// Kernel 2: fill. Identical store sweep to the 7.2 TB/s memset; the only
// addition on the fast path is ONE warp-broadcast mask load + uniform branch.
// idx -> l4 = idx&511 (fixed per thread!), d = (idx>>9)&1023, b = idx>>19,
// each k-iteration adds STRIDE -> b += 2, l4/d unchanged.
// ---------------------------------------------------------------------------
__global__ void __launch_bounds__(ZTPB) fill_kernel(
    const int* __restrict__ x,
    const float* __restrict__ w,
    float4* __restrict__ out)
{
    unsigned idx = blockIdx.x * ZTPB + threadIdx.x;
    const int l4 = idx & 511;
    const int d  = (idx >> 9) & 1023;
    const int b0 = idx >> 19;             // 0 or 1

    const unsigned m = g_mask[l4 >> 5];   // same word for whole warp
    if (!((m >> (l4 & 31)) & 1u)) {
        const float4 z = make_float4(0.f, 0.f, 0.f, 0.f);
        #pragma unroll
        for (int k = 0; k < ZITER; k++) {
            __stcs(out + idx, z);
            idx += STRIDE;
        }
    } else {
        // Rare: ~2.5% of threads, inputs are L2-hot (x=128KB, w rows<20=80KB)
        const int l0 = l4 << 2;
        #pragma unroll
        for (int k = 0; k < ZITER; k++) {
            int b = b0 + 2 * k;
            int base = l0 * B_DIM + b;
            int t0 = __ldg(x + base);
            int t1 = __ldg(x + base + B_DIM);
            int t2 = __ldg(x + base + 2 * B_DIM);
            int t3 = __ldg(x + base + 3 * B_DIM);
            float4 v;
            v.x = (t0 < MAXTOK) ? __ldg(w + (size_t)t0 * D_DIM + d) * SCALE : 0.f;
            v.y = (t1 < MAXTOK) ? __ldg(w + (size_t)t1 * D_DIM + d) * SCALE : 0.f;
            v.z = (t2 < MAXTOK) ? __ldg(w + (size_t)t2 * D_DIM + d) * SCALE : 0.f;
            v.w = (t3 < MAXTOK) ? __ldg(w + (size_t)t3 * D_DIM + d) * SCALE : 0.f;
            __stcs(out + idx, v);
            idx += STRIDE;
        }
    }
}

// ---------------------------------------------------------------------------
extern "C" void kernel_launch(void* const* d_in, const int* in_sizes, int n_in,
                              void* d_out, int out_size)
{
    const int*   x = (const int*)d_in[0];
    const float* w = (const float*)d_in[1];

    mask_kernel<<<16, 32>>>(x);
    fill_kernel<<<ZBLOCKS, ZTPB>>>(x, w, (float4*)d_out);
}

// round 6
// speedup vs baseline: 1.1117x; 1.1117x over previous
#include <cuda_runtime.h>
#include <cuda_bf16.h>

// x:       (L=2048, B=16) int32   -> x[l*16 + b]
// embed_w: (V=50257, D=1024) fp32 -> w[t*1024 + d]
// out:     (B=16, D=1024, L=2048) fp32 -> out[b*D*L + d*L + l]
// rows with token >= 20 are zero; output scaled by sqrt(8).

#define L_DIM   2048
#define B_DIM   16
#define D_DIM   1024
#define MAXTOK  20
#define SCALE   2.8284271247461903f  // sqrt(8)

#define ZBLOCKS 4096
#define ZTPB    256
#define ZITER   8            // 4096*256*8 = 8388608 float4
#define STRIDE  (1u << 20)   // ZBLOCKS*ZTPB

// Bit g (of 512): any token < MAXTOK for l in [4g,4g+4), any b. 16 words.
__device__ unsigned g_mask[16];

// ---------------------------------------------------------------------------
// Kernel 1: build 512-bit mask. 16 blocks x 1 warp, coalesced int4 reads.
// (validated: R5 passed with rel_err 0 using this exact kernel)
// ---------------------------------------------------------------------------
__global__ void __launch_bounds__(32) mask_kernel(const int* __restrict__ x)
{
    const int wi   = blockIdx.x;
    const int lane = threadIdx.x;
    const int4* src = (const int4*)x + wi * 512;

    unsigned word = 0;
    #pragma unroll
    for (int j = 0; j < 16; j++) {
        int4 v = __ldg(src + j * 32 + lane);
        int hit = (v.x < MAXTOK) | (v.y < MAXTOK) |
                  (v.z < MAXTOK) | (v.w < MAXTOK);
        unsigned bal = __ballot_sync(0xFFFFFFFFu, hit);
        word |= ((bal & 0xFFFFu) ? 1u : 0u) << (2 * j);
        word |= ((bal >> 16)     ? 1u : 0u) << (2 * j + 1);
    }
    if (lane == 0) g_mask[wi] = word;
}

// ---------------------------------------------------------------------------
// Kernel 2: fill + warp-cooperative fixup.
// EVERY thread runs the proven memset sweep (7.2 TB/s pattern, untouched).
// Then each warp (uniform d, uniform b-parity, 32 aligned l4s = one mask
// word) checks its word; hit warps cooperatively rewrite the rare rows.
// __syncwarp() orders the fixup stores after the zero stores (same warp).
// ---------------------------------------------------------------------------
__global__ void __launch_bounds__(ZTPB) fill_kernel(
    const int* __restrict__ x,
    const float* __restrict__ w,
    float4* __restrict__ out)
{
    const unsigned idx0 = blockIdx.x * ZTPB + threadIdx.x;

    // --- unconditional zero sweep (do not touch: at store ceiling) ---
    const float4 z = make_float4(0.f, 0.f, 0.f, 0.f);
    unsigned idx = idx0;
    #pragma unroll
    for (int k = 0; k < ZITER; k++) {
        __stcs(out + idx, z);
        idx += STRIDE;
    }

    // --- warp-uniform predicate ---
    const int l4 = idx0 & 511;               // lane-varying, warp spans an
    unsigned word = g_mask[l4 >> 5];         // aligned 32-window -> 1 word
    if (word == 0) return;                   // 45% of warps: done

    __syncwarp();                            // order fixup after zero stores

    // --- cooperative fixup: 32 lanes cover 4 l x 8 b per set bit ---
    const int d     = (idx0 >> 9) & 1023;    // warp-uniform
    const int b0    = idx0 >> 19;            // warp-uniform parity (0/1)
    const int lane  = threadIdx.x & 31;
    const int l4w   = l4 & ~31;              // warp's l4 window base
    const int l_off = lane >> 3;             // 0..3
    const int b     = b0 + 2 * (lane & 7);   // parity-matched b
    float* outf = (float*)out;

    while (word) {                           // uniform loop, ~1 iteration
        int g = __ffs(word) - 1;
        word &= word - 1;
        int l = ((l4w + g) << 2) + l_off;
        int t = __ldg(x + l * B_DIM + b);    // 32 lanes: 256B region
        if (t < MAXTOK) {
            outf[(size_t)b * (D_DIM * L_DIM) + (size_t)d * L_DIM + l] =
                __ldg(w + (size_t)t * D_DIM + d) * SCALE;
        }
    }
}

// ---------------------------------------------------------------------------
extern "C" void kernel_launch(void* const* d_in, const int* in_sizes, int n_in,
                              void* d_out, int out_size)
{
    const int*   x = (const int*)d_in[0];
    const float* w = (const float*)d_in[1];

    mask_kernel<<<16, 32>>>(x);
    fill_kernel<<<ZBLOCKS, ZTPB>>>(x, w, (float4*)d_out);
}